// round 15
// baseline (speedup 1.0000x reference)
#include <cuda_runtime.h>
#include <cuda_fp16.h>
#include <math.h>
#include <stdint.h>

#define TOKENS   65536
#define DDIM     256
#define KCODES   4096
#define HW       1024
#define OUT_ELEMS 16777216
#define NBMMA    2048            // 32 tokens per CTA
#define NBRES    8192            // 8 tokens per CTA
#define BSTAGE   16384           // 32-code ntile: 16*4*32*2 u32 = 16KB
#define ESCALE   4096.0f         // e pre-scale (2^12, lossless)
#define DSCALE   (-2.0f / 4096.0f)
typedef unsigned long long u64;

// ---------------- global scratch ----------------
// fp16 A frags (m16n8k16): [mt(4096)][kt(16)][lane(32)][4] u32  (128 u32/token)
__device__ uint32_t g_x1f[TOKENS * 128];
// fp16 B frags (e * 4096): [nt(128)][kt(16)][nb(4)][lane(32)][2] u32
__device__ uint32_t g_e1f[128 * 4096];
__device__ float g_xT[TOKENS * DDIM];    // fp32 x token-major (rescore)
__device__ float g_xn2[TOKENS];
__device__ float g_enorm2[KCODES];
__device__ int   g_cand[TOKENS * 8];
__device__ int   g_idx[TOKENS];
__device__ float g_partial[NBRES];
__device__ int   g_counts[KCODES];

#define CP_ASYNC16(dst, src) \
    asm volatile("cp.async.cg.shared.global [%0], [%1], 16;" :: "r"(dst), "l"(src))
#define CP_COMMIT()  asm volatile("cp.async.commit_group;" ::: "memory")
#define CP_WAIT_0()  asm volatile("cp.async.wait_group 0;" ::: "memory")
#define CP_WAIT_1()  asm volatile("cp.async.wait_group 1;" ::: "memory")
#define CP_WAIT_2()  asm volatile("cp.async.wait_group 2;" ::: "memory")

__device__ __forceinline__ uint32_t su32(const void* p) {
    uint32_t a;
    asm("{ .reg .u64 t; cvta.to.shared.u64 t, %1; cvt.u32.u64 %0, t; }"
        : "=r"(a) : "l"(p));
    return a;
}
__device__ __forceinline__ uint32_t pack_hf2(float lo, float hi) {
    uint32_t l = (uint32_t)__half_as_ushort(__float2half(lo));
    uint32_t h = (uint32_t)__half_as_ushort(__float2half(hi));
    return l | (h << 16);
}
__device__ __forceinline__ void mma16816h(uint32_t* c, const uint32_t* a,
                                          uint32_t b0, uint32_t b1) {
    asm volatile(
        "mma.sync.aligned.m16n8k16.row.col.f16.f16.f16.f16 "
        "{%0,%1},{%2,%3,%4,%5},{%6,%7},{%0,%1};"
        : "+r"(c[0]), "+r"(c[1])
        : "r"(a[0]), "r"(a[1]), "r"(a[2]), "r"(a[3]), "r"(b0), "r"(b1));
}
__device__ __forceinline__ float hlo(uint32_t v) {
    return __half2float(__ushort_as_half((unsigned short)(v & 0xffff)));
}
__device__ __forceinline__ float hhi(uint32_t v) {
    return __half2float(__ushort_as_half((unsigned short)(v >> 16)));
}
__device__ __forceinline__ void ins3(u64 p, u64* s) {
    if (p >= s[2]) return;
    s[2] = p;
    if (s[2] < s[1]) { u64 t = s[1]; s[1] = s[2]; s[2] = t; }
    if (s[1] < s[0]) { u64 t = s[0]; s[0] = s[1]; s[1] = t; }
}
__device__ __forceinline__ void ins8(u64 p, u64* s) {
    if (p >= s[7]) return;
    s[7] = p;
    #pragma unroll
    for (int i = 7; i > 0; i--)
        if (s[i] < s[i-1]) { u64 t = s[i-1]; s[i-1] = s[i]; s[i] = t; }
}

// ---------------------------------------------------------------------------
// Prep E: 128 codes (4 ntiles of 32) per CTA; |e|^2 + scaled fp16 frags; hist=0
// ---------------------------------------------------------------------------
__global__ void __launch_bounds__(256, 1) k_prep_e(const float* __restrict__ emb) {
    extern __shared__ float sp[];          // [128][260]
    const int t = threadIdx.x;
    const float* src = emb + (size_t)blockIdx.x * 128 * DDIM;
    #pragma unroll
    for (int j = 0; j < 32; j++) {
        int i = t + j * 256;
        int row = i >> 6, c4 = i & 63;
        float4 v = *(const float4*)(src + row * DDIM + c4 * 4);
        *(float4*)&sp[row * 260 + c4 * 4] = v;
    }
    __syncthreads();
    if (t < 128) {
        float s = 0.f;
        #pragma unroll 8
        for (int d = 0; d < DDIM; d++) { float v = sp[t * 260 + d]; s = fmaf(v, v, s); }
        g_enorm2[blockIdx.x * 128 + t] = s;
        g_counts[blockIdx.x * 128 + t] = 0;
    }
    // frag layout per 32-code ntile: i2 = ((kt*4+nb)*32+lane)*2 + reg
    uint32_t* dst = g_e1f + (size_t)blockIdx.x * 16384;
    #pragma unroll
    for (int j = 0; j < 64; j++) {
        int i = t + j * 256;               // 0..16383
        int snt = i >> 12, i2 = i & 4095;
        int reg = i2 & 1, lane = (i2 >> 1) & 31, nb = (i2 >> 6) & 3, kt = i2 >> 8;
        int gid = lane >> 2, tig = lane & 3;
        int nl = snt * 32 + nb * 8 + gid;  // local code 0..127
        int q = kt * 8 + reg * 4 + tig;    // k-pair
        dst[i] = pack_hf2(sp[nl * 260 + 2 * q] * ESCALE,
                          sp[nl * 260 + 2 * q + 1] * ESCALE);
    }
}

// ---------------------------------------------------------------------------
// Prep X: transpose, |x|^2, fp32 token-major, coalesced fp16 frag writes
// ---------------------------------------------------------------------------
__global__ void __launch_bounds__(256, 1) k_prep_x(const float* __restrict__ x) {
    extern __shared__ float As[];   // [d][m] 256*132
    const int t = threadIdx.x;
    const int base = blockIdx.x * 128;
    const int b = base >> 10, hw0 = base & 1023;
    const float* xb = x + (size_t)b * (DDIM * HW) + hw0;
    {
        int lane4 = (t & 31) * 4, d0 = t >> 5;
        #pragma unroll
        for (int dd = 0; dd < DDIM; dd += 8) {
            int d = dd + d0;
            float4 v = *(const float4*)(xb + (size_t)d * HW + lane4);
            *(float4*)&As[d * 132 + lane4] = v;
        }
    }
    __syncthreads();
    if (t < 128) {
        float s = 0.f;
        #pragma unroll 8
        for (int d = 0; d < DDIM; d++) { float v = As[d * 132 + t]; s = fmaf(v, v, s); }
        g_xn2[base + t] = s;
    }
    for (int i = t; i < 128 * 256; i += 256) {
        int m = i >> 8, d = i & 255;
        g_xT[(size_t)(base + m) * DDIM + d] = As[d * 132 + m];
    }
    // frags: i = mtl*2048 + kt*128 + lane*4 + reg  (128 u32/token)
    uint32_t* dst = g_x1f + (size_t)base * 128;
    #pragma unroll
    for (int j = 0; j < 64; j++) {
        int i = t + j * 256;
        int reg = i & 3, lane = (i >> 2) & 31, kt = (i >> 7) & 15, mtl = i >> 11;
        int gid = lane >> 2, tig = lane & 3;
        int rsel = reg & 1, khalf = reg >> 1;
        int m = mtl * 16 + rsel * 8 + gid;
        int q = kt * 8 + khalf * 4 + tig;
        dst[i] = pack_hf2(As[(2 * q) * 132 + m], As[(2 * q + 1) * 132 + m]);
    }
}

// ---------------------------------------------------------------------------
// Main: fp16 mma.sync, 32-token CTA (fine-grained tail), A in registers,
// 4-stage B ring, 1 barrier/ntile. SMEM: 4 x 16KB = 65536.
// Warp w: mt = w&1 (16-token tile), h = w>>1 (one 8-code nb group per kt)
// ---------------------------------------------------------------------------
__device__ __forceinline__ void load_b(uint32_t smb, int nt, int t) {
    const char* src = (const char*)g_e1f + (size_t)nt * 16384;
    uint32_t dst = smb + (nt & 3) * BSTAGE;
    #pragma unroll
    for (int j = 0; j < 4; j++) {
        int c = t + j * 256;               // linear copy
        CP_ASYNC16(dst + c * 16, src + c * 16);
    }
}

__global__ void __launch_bounds__(256, 2) k_mma() {
    extern __shared__ char sm[];
    const uint32_t smb = su32(sm);
    const int t = threadIdx.x, wid = t >> 5, lane = t & 31;
    const int gid = lane >> 2, tig = lane & 3;
    const int base = blockIdx.x * 32;
    const int mt = wid & 1;                 // local m-tile (16 tokens)
    const int h  = wid >> 1;                // nb group 0..3

    // prologue: 3-deep B prefetch
    load_b(smb, 0, t); CP_COMMIT();
    load_b(smb, 1, t); CP_COMMIT();
    load_b(smb, 2, t); CP_COMMIT();

    // A fragments resident in registers for the whole loop (reused 128x)
    uint32_t A[16][4];
    {
        const uint32_t* asrc = g_x1f + (size_t)base * 128 + mt * 2048 + lane * 4;
        #pragma unroll
        for (int kt = 0; kt < 16; kt++)
            *(uint4*)A[kt] = *(const uint4*)(asrc + kt * 128);
    }

    const int tk0 = base + mt * 16 + gid;
    const float xr0 = g_xn2[tk0], xr1 = g_xn2[tk0 + 8];

    u64 L[2][3];
    #pragma unroll
    for (int l = 0; l < 2; l++)
        #pragma unroll
        for (int i = 0; i < 3; i++) L[l][i] = ~0ULL;

    for (int nt = 0; nt < 128; nt++) {
        if (nt <= 125)      { CP_WAIT_2(); }
        else if (nt == 126) { CP_WAIT_1(); }
        else                { CP_WAIT_0(); }
        __syncthreads();                       // publish loads + retire nt-1
        if (nt + 3 < 128) { load_b(smb, nt + 3, t); CP_COMMIT(); }

        const uint32_t* Bf = (const uint32_t*)(sm + (nt & 3) * BSTAGE);
        uint32_t acc[2];                       // fp16x2 accumulators (1 nb)
        acc[0] = acc[1] = 0u;

        #pragma unroll
        for (int kt = 0; kt < 16; kt++) {
            uint2 b0 = *(const uint2*)(Bf + ((kt * 4 + h) * 32 + lane) * 2);
            mma16816h(acc, A[kt], b0.x, b0.y);
        }

        // fold: d = fma(DSCALE, dot_scaled, xn2 + en2); codes ascending; '<'
        {
            int code0 = nt * 32 + h * 8 + tig * 2;
            float en0 = __ldg(&g_enorm2[code0]);
            float en1 = __ldg(&g_enorm2[code0 + 1]);
            float d;
            d = fmaf(DSCALE, hlo(acc[0]), xr0 + en0);
            ins3(((u64)__float_as_uint(d) << 32) | (unsigned)code0,       L[0]);
            d = fmaf(DSCALE, hhi(acc[0]), xr0 + en1);
            ins3(((u64)__float_as_uint(d) << 32) | (unsigned)(code0 + 1), L[0]);
            d = fmaf(DSCALE, hlo(acc[1]), xr1 + en0);
            ins3(((u64)__float_as_uint(d) << 32) | (unsigned)code0,       L[1]);
            d = fmaf(DSCALE, hhi(acc[1]), xr1 + en1);
            ins3(((u64)__float_as_uint(d) << 32) | (unsigned)(code0 + 1), L[1]);
        }
    }

    // merge: 16 buckets (h,tig) x top-3 per token -> top-8
    __syncthreads();
    u64* cm = (u64*)sm;                        // [32][48] = 12KB (reuses B ring)
    #pragma unroll
    for (int l = 0; l < 2; l++) {
        int tok = mt * 16 + l * 8 + gid;
        #pragma unroll
        for (int i = 0; i < 3; i++)
            cm[(size_t)tok * 48 + (h * 4 + tig) * 3 + i] = L[l][i];
    }
    __syncthreads();
    if (t < 32) {
        u64 top[8];
        #pragma unroll
        for (int i = 0; i < 8; i++) top[i] = ~0ULL;
        #pragma unroll
        for (int i = 0; i < 48; i++) ins8(cm[(size_t)t * 48 + i], top);
        #pragma unroll
        for (int i = 0; i < 8; i++)
            g_cand[(size_t)(base + t) * 8 + i] = (int)(top[i] & 0xffffffffu);
    }
}

// ---------------------------------------------------------------------------
// Rescore: exact fp32 distance for 8 candidates per token (warp per token)
// ---------------------------------------------------------------------------
__global__ void __launch_bounds__(256, 4) k_rescore(const float* __restrict__ emb) {
    const int t = threadIdx.x, wid = t >> 5, lane = t & 31;
    const int n = blockIdx.x * 8 + wid;
    const float4* xr = (const float4*)(g_xT + (size_t)n * DDIM + lane * 8);
    float4 xa = xr[0], xb = xr[1];
    float xn2 = g_xn2[n];
    u64 best = ~0ULL;
    #pragma unroll
    for (int i = 0; i < 8; i++) {
        int c = g_cand[(size_t)n * 8 + i];
        const float4* er = (const float4*)(emb + (size_t)c * DDIM + lane * 8);
        float4 ea = er[0], eb = er[1];
        float p = 0.f;
        p = fmaf(xa.x, ea.x, p); p = fmaf(xa.y, ea.y, p);
        p = fmaf(xa.z, ea.z, p); p = fmaf(xa.w, ea.w, p);
        p = fmaf(xb.x, eb.x, p); p = fmaf(xb.y, eb.y, p);
        p = fmaf(xb.z, eb.z, p); p = fmaf(xb.w, eb.w, p);
        #pragma unroll
        for (int o = 16; o > 0; o >>= 1) p += __shfl_xor_sync(0xffffffffu, p, o);
        float A = xn2 + __ldg(&g_enorm2[c]);
        float d = fmaf(-2.f, p, A);
        u64 pk = ((u64)__float_as_uint(d) << 32) | (unsigned)c;
        if (pk < best) best = pk;
    }
    __shared__ float wb[8];
    if (lane == 0) {
        g_idx[n] = (int)(best & 0xffffffffu);
        wb[wid] = __uint_as_float((unsigned)(best >> 32));
    }
    __syncthreads();
    if (t == 0) {
        float s = 0.f;
        #pragma unroll
        for (int i = 0; i < 8; i++) s += wb[i];
        g_partial[blockIdx.x] = s;
    }
}

// ---------------------------------------------------------------------------
// Gather + histogram
// ---------------------------------------------------------------------------
__global__ void __launch_bounds__(256, 1)
k_gather(const float* __restrict__ emb, float* __restrict__ out) {
    extern __shared__ float rows[];      // 128 * 257
    __shared__ int sidx[128];
    const int t = threadIdx.x;
    const int base = blockIdx.x * 128;
    if (t < 128) {
        int id = g_idx[base + t];
        sidx[t] = id;
        atomicAdd(&g_counts[id], 1);
    }
    __syncthreads();
    const int w = t >> 5, lane = t & 31;
    for (int r = w; r < 128; r += 8) {
        const float* er = emb + (size_t)sidx[r] * DDIM;
        #pragma unroll
        for (int q = 0; q < 8; q++)
            rows[r * 257 + lane + q * 32] = er[lane + q * 32];
    }
    __syncthreads();
    const int b = base >> 10, hw0 = base & 1023;
    float* ob = out + (size_t)b * (DDIM * HW) + hw0;
    const int m = t & 127, ch = t >> 7;
    #pragma unroll 4
    for (int cc = 0; cc < 128; cc++) {
        int c = cc * 2 + ch;
        ob[(size_t)c * HW + m] = rows[m * 257 + c];
    }
}

// ---------------------------------------------------------------------------
// Loss + perplexity
// ---------------------------------------------------------------------------
__global__ void k_final(float* __restrict__ out) {
    __shared__ float sh[1024];
    const int t = threadIdx.x;
    float s = 0.f;
    for (int i = t; i < NBRES; i += 1024) s += g_partial[i];
    sh[t] = s; __syncthreads();
    for (int o = 512; o > 0; o >>= 1) {
        if (t < o) sh[t] += sh[t + o];
        __syncthreads();
    }
    if (t == 0) out[OUT_ELEMS] = 1.25f * sh[0] / 16777216.0f;
    __syncthreads();
    float e = 0.f;
    for (int k = t; k < KCODES; k += 1024) {
        float p = (float)g_counts[k] * (1.0f / 65536.0f);
        e -= p * logf(p + 1e-10f);
    }
    sh[t] = e; __syncthreads();
    for (int o = 512; o > 0; o >>= 1) {
        if (t < o) sh[t] += sh[t + o];
        __syncthreads();
    }
    if (t == 0) out[OUT_ELEMS + 1] = expf(sh[0]);
}

// ---------------------------------------------------------------------------
extern "C" void kernel_launch(void* const* d_in, const int* in_sizes, int n_in,
                              void* d_out, int out_size) {
    const float* x   = (const float*)d_in[0];
    const float* emb = (const float*)d_in[1];
    float* out = (float*)d_out;

    const int SMEME = 128 * 260 * sizeof(float);   // 133120
    const int SMEMX = 256 * 132 * sizeof(float);   // 135168
    const int SMEMM = 4 * BSTAGE;                  // 65536 (B ring only)
    const int SMEMG = 128 * 257 * sizeof(float);   // 131584
    cudaFuncSetAttribute(k_prep_e, cudaFuncAttributeMaxDynamicSharedMemorySize, SMEME);
    cudaFuncSetAttribute(k_prep_x, cudaFuncAttributeMaxDynamicSharedMemorySize, SMEMX);
    cudaFuncSetAttribute(k_mma,    cudaFuncAttributeMaxDynamicSharedMemorySize, SMEMM);
    cudaFuncSetAttribute(k_gather, cudaFuncAttributeMaxDynamicSharedMemorySize, SMEMG);

    k_prep_e <<<KCODES / 128, 256, SMEME>>>(emb);
    k_prep_x <<<TOKENS / 128, 256, SMEMX>>>(x);
    k_mma    <<<NBMMA, 256, SMEMM>>>();
    k_rescore<<<NBRES, 256>>>(emb);
    k_gather <<<TOKENS / 128, 256, SMEMG>>>(emb, out);
    k_final  <<<1, 1024>>>(out);
}

// round 16
// speedup vs baseline: 1.2962x; 1.2962x over previous
#include <cuda_runtime.h>
#include <cuda_fp16.h>
#include <math.h>
#include <stdint.h>

#define TOKENS   65536
#define DDIM     256
#define KCODES   4096
#define HW       1024
#define OUT_ELEMS 16777216
#define NBMMA    2048            // 2 CTAs per 64-token block (code-space split)
#define NBRES    8192            // 8 tokens per CTA
#define BSTAGE   16384           // 32-code ntile: 16*4*32*2 u32 = 16KB
#define ESCALE   4096.0f         // e pre-scale (2^12, lossless)
#define DSCALE   (-2.0f / 4096.0f)
typedef unsigned long long u64;

// ---------------- global scratch ----------------
// fp16 A frags (m16n8k16): [mt(4096)][kt(16)][lane(32)][4] u32  (128 u32/token)
__device__ uint32_t g_x1f[TOKENS * 128];
// fp16 B frags (e * 4096): [nt(128)][kt(16)][nb(4)][lane(32)][2] u32
__device__ uint32_t g_e1f[128 * 4096];
__device__ float g_xT[TOKENS * DDIM];    // fp32 x token-major (rescore)
__device__ float g_xn2[TOKENS];
__device__ float g_enorm2[KCODES];
__device__ int   g_cand[TOKENS * 8];
__device__ int   g_idx[TOKENS];
__device__ float g_partial[NBRES];
__device__ int   g_counts[KCODES];

#define CP_ASYNC16(dst, src) \
    asm volatile("cp.async.cg.shared.global [%0], [%1], 16;" :: "r"(dst), "l"(src))
#define CP_COMMIT()  asm volatile("cp.async.commit_group;" ::: "memory")
#define CP_WAIT_0()  asm volatile("cp.async.wait_group 0;" ::: "memory")
#define CP_WAIT_1()  asm volatile("cp.async.wait_group 1;" ::: "memory")
#define CP_WAIT_2()  asm volatile("cp.async.wait_group 2;" ::: "memory")

__device__ __forceinline__ uint32_t su32(const void* p) {
    uint32_t a;
    asm("{ .reg .u64 t; cvta.to.shared.u64 t, %1; cvt.u32.u64 %0, t; }"
        : "=r"(a) : "l"(p));
    return a;
}
__device__ __forceinline__ uint32_t pack_hf2(float lo, float hi) {
    uint32_t l = (uint32_t)__half_as_ushort(__float2half(lo));
    uint32_t h = (uint32_t)__half_as_ushort(__float2half(hi));
    return l | (h << 16);
}
__device__ __forceinline__ void mma16816h(uint32_t* c, const uint32_t* a,
                                          uint32_t b0, uint32_t b1) {
    asm volatile(
        "mma.sync.aligned.m16n8k16.row.col.f16.f16.f16.f16 "
        "{%0,%1},{%2,%3,%4,%5},{%6,%7},{%0,%1};"
        : "+r"(c[0]), "+r"(c[1])
        : "r"(a[0]), "r"(a[1]), "r"(a[2]), "r"(a[3]), "r"(b0), "r"(b1));
}
__device__ __forceinline__ float hlo(uint32_t v) {
    return __half2float(__ushort_as_half((unsigned short)(v & 0xffff)));
}
__device__ __forceinline__ float hhi(uint32_t v) {
    return __half2float(__ushort_as_half((unsigned short)(v >> 16)));
}
__device__ __forceinline__ void ins3(u64 p, u64* s) {
    if (p >= s[2]) return;
    s[2] = p;
    if (s[2] < s[1]) { u64 t = s[1]; s[1] = s[2]; s[2] = t; }
    if (s[1] < s[0]) { u64 t = s[0]; s[0] = s[1]; s[1] = t; }
}
__device__ __forceinline__ void ins4(u64 p, u64* s) {
    if (p >= s[3]) return;
    s[3] = p;
    if (s[3] < s[2]) { u64 t = s[2]; s[2] = s[3]; s[3] = t; }
    if (s[2] < s[1]) { u64 t = s[1]; s[1] = s[2]; s[2] = t; }
    if (s[1] < s[0]) { u64 t = s[0]; s[0] = s[1]; s[1] = t; }
}

// ---------------------------------------------------------------------------
// Prep E: 128 codes (4 ntiles of 32) per CTA; |e|^2 + scaled fp16 frags; hist=0
// ---------------------------------------------------------------------------
__global__ void __launch_bounds__(256, 1) k_prep_e(const float* __restrict__ emb) {
    extern __shared__ float sp[];          // [128][260]
    const int t = threadIdx.x;
    const float* src = emb + (size_t)blockIdx.x * 128 * DDIM;
    #pragma unroll
    for (int j = 0; j < 32; j++) {
        int i = t + j * 256;
        int row = i >> 6, c4 = i & 63;
        float4 v = *(const float4*)(src + row * DDIM + c4 * 4);
        *(float4*)&sp[row * 260 + c4 * 4] = v;
    }
    __syncthreads();
    if (t < 128) {
        float s = 0.f;
        #pragma unroll 8
        for (int d = 0; d < DDIM; d++) { float v = sp[t * 260 + d]; s = fmaf(v, v, s); }
        g_enorm2[blockIdx.x * 128 + t] = s;
        g_counts[blockIdx.x * 128 + t] = 0;
    }
    // frag layout per 32-code ntile: i2 = ((kt*4+nb)*32+lane)*2 + reg
    uint32_t* dst = g_e1f + (size_t)blockIdx.x * 16384;
    #pragma unroll
    for (int j = 0; j < 64; j++) {
        int i = t + j * 256;               // 0..16383
        int snt = i >> 12, i2 = i & 4095;
        int reg = i2 & 1, lane = (i2 >> 1) & 31, nb = (i2 >> 6) & 3, kt = i2 >> 8;
        int gid = lane >> 2, tig = lane & 3;
        int nl = snt * 32 + nb * 8 + gid;  // local code 0..127
        int q = kt * 8 + reg * 4 + tig;    // k-pair
        dst[i] = pack_hf2(sp[nl * 260 + 2 * q] * ESCALE,
                          sp[nl * 260 + 2 * q + 1] * ESCALE);
    }
}

// ---------------------------------------------------------------------------
// Prep X: transpose, |x|^2, fp32 token-major, coalesced fp16 frag writes
// ---------------------------------------------------------------------------
__global__ void __launch_bounds__(256, 1) k_prep_x(const float* __restrict__ x) {
    extern __shared__ float As[];   // [d][m] 256*132
    const int t = threadIdx.x;
    const int base = blockIdx.x * 128;
    const int b = base >> 10, hw0 = base & 1023;
    const float* xb = x + (size_t)b * (DDIM * HW) + hw0;
    {
        int lane4 = (t & 31) * 4, d0 = t >> 5;
        #pragma unroll
        for (int dd = 0; dd < DDIM; dd += 8) {
            int d = dd + d0;
            float4 v = *(const float4*)(xb + (size_t)d * HW + lane4);
            *(float4*)&As[d * 132 + lane4] = v;
        }
    }
    __syncthreads();
    if (t < 128) {
        float s = 0.f;
        #pragma unroll 8
        for (int d = 0; d < DDIM; d++) { float v = As[d * 132 + t]; s = fmaf(v, v, s); }
        g_xn2[base + t] = s;
    }
    for (int i = t; i < 128 * 256; i += 256) {
        int m = i >> 8, d = i & 255;
        g_xT[(size_t)(base + m) * DDIM + d] = As[d * 132 + m];
    }
    // frags: i = mtl*2048 + kt*128 + lane*4 + reg  (128 u32/token)
    uint32_t* dst = g_x1f + (size_t)base * 128;
    #pragma unroll
    for (int j = 0; j < 64; j++) {
        int i = t + j * 256;
        int reg = i & 3, lane = (i >> 2) & 31, kt = (i >> 7) & 15, mtl = i >> 11;
        int gid = lane >> 2, tig = lane & 3;
        int rsel = reg & 1, khalf = reg >> 1;
        int m = mtl * 16 + rsel * 8 + gid;
        int q = kt * 8 + khalf * 4 + tig;
        dst[i] = pack_hf2(As[(2 * q) * 132 + m], As[(2 * q + 1) * 132 + m]);
    }
}

// ---------------------------------------------------------------------------
// Main: fp16 mma.sync, 64-token x half-codebook jobs (R14 inner loop),
// A in registers, 4-stage B ring, 1 barrier/ntile. SMEM: 4 x 16KB.
// CTA = (block >> 1) token-block, (block & 1) code half -> cand slots 0-3/4-7
// ---------------------------------------------------------------------------
__device__ __forceinline__ void load_b(uint32_t smb, int nt, int t) {
    const char* src = (const char*)g_e1f + (size_t)nt * 16384;
    uint32_t dst = smb + (nt & 3) * BSTAGE;
    #pragma unroll
    for (int j = 0; j < 4; j++) {
        int c = t + j * 256;               // linear copy
        CP_ASYNC16(dst + c * 16, src + c * 16);
    }
}

__global__ void __launch_bounds__(256, 2) k_mma() {
    extern __shared__ char sm[];
    const uint32_t smb = su32(sm);
    const int t = threadIdx.x, wid = t >> 5, lane = t & 31;
    const int gid = lane >> 2, tig = lane & 3;
    const int base = (blockIdx.x >> 1) * 64;
    const int half = blockIdx.x & 1;
    const int nt0  = half * 64;             // ntile range [nt0, nt0+64)
    const int mt = wid & 3;                 // local m-tile (16 tokens)
    const int h  = wid >> 2;                // nb pair: nb = h*2, h*2+1

    // prologue: 3-deep B prefetch
    load_b(smb, nt0 + 0, t); CP_COMMIT();
    load_b(smb, nt0 + 1, t); CP_COMMIT();
    load_b(smb, nt0 + 2, t); CP_COMMIT();

    // A fragments resident in registers for the whole loop (reused 64x)
    uint32_t A[16][4];
    {
        const uint32_t* asrc = g_x1f + (size_t)base * 128 + mt * 2048 + lane * 4;
        #pragma unroll
        for (int kt = 0; kt < 16; kt++)
            *(uint4*)A[kt] = *(const uint4*)(asrc + kt * 128);
    }

    const int tk0 = base + mt * 16 + gid;
    const float xr0 = g_xn2[tk0], xr1 = g_xn2[tk0 + 8];

    u64 L[2][3];
    #pragma unroll
    for (int l = 0; l < 2; l++)
        #pragma unroll
        for (int i = 0; i < 3; i++) L[l][i] = ~0ULL;

    for (int ii = 0; ii < 64; ii++) {
        const int nt = nt0 + ii;
        if (ii <= 61)      { CP_WAIT_2(); }
        else if (ii == 62) { CP_WAIT_1(); }
        else               { CP_WAIT_0(); }
        __syncthreads();                       // publish loads + retire prev
        if (ii + 3 < 64) { load_b(smb, nt + 3, t); CP_COMMIT(); }

        const uint32_t* Bf = (const uint32_t*)(sm + (nt & 3) * BSTAGE);
        uint32_t acc[2][2];                    // fp16x2 accumulators
        acc[0][0] = acc[0][1] = acc[1][0] = acc[1][1] = 0u;

        #pragma unroll
        for (int kt = 0; kt < 16; kt++) {
            uint2 b0 = *(const uint2*)(Bf + ((kt * 4 + h * 2 + 0) * 32 + lane) * 2);
            uint2 b1 = *(const uint2*)(Bf + ((kt * 4 + h * 2 + 1) * 32 + lane) * 2);
            mma16816h(acc[0], A[kt], b0.x, b0.y);
            mma16816h(acc[1], A[kt], b1.x, b1.y);
        }

        // fold: d = fma(DSCALE, dot_scaled, xn2 + en2); codes ascending; '<'
        #pragma unroll
        for (int nb2 = 0; nb2 < 2; nb2++) {
            int code0 = nt * 32 + (h * 2 + nb2) * 8 + tig * 2;
            float en0 = __ldg(&g_enorm2[code0]);
            float en1 = __ldg(&g_enorm2[code0 + 1]);
            float d;
            d = fmaf(DSCALE, hlo(acc[nb2][0]), xr0 + en0);
            ins3(((u64)__float_as_uint(d) << 32) | (unsigned)code0,       L[0]);
            d = fmaf(DSCALE, hhi(acc[nb2][0]), xr0 + en1);
            ins3(((u64)__float_as_uint(d) << 32) | (unsigned)(code0 + 1), L[0]);
            d = fmaf(DSCALE, hlo(acc[nb2][1]), xr1 + en0);
            ins3(((u64)__float_as_uint(d) << 32) | (unsigned)code0,       L[1]);
            d = fmaf(DSCALE, hhi(acc[nb2][1]), xr1 + en1);
            ins3(((u64)__float_as_uint(d) << 32) | (unsigned)(code0 + 1), L[1]);
        }
    }

    // merge: 8 buckets (h,tig) x top-3 per token -> top-4 of this code half
    __syncthreads();
    u64* cm = (u64*)sm;                        // [64][24] = 12KB (reuses B ring)
    #pragma unroll
    for (int l = 0; l < 2; l++) {
        int tok = mt * 16 + l * 8 + gid;
        #pragma unroll
        for (int i = 0; i < 3; i++)
            cm[(size_t)tok * 24 + (h * 4 + tig) * 3 + i] = L[l][i];
    }
    __syncthreads();
    if (t < 64) {
        u64 top[4];
        #pragma unroll
        for (int i = 0; i < 4; i++) top[i] = ~0ULL;
        #pragma unroll
        for (int i = 0; i < 24; i++) ins4(cm[(size_t)t * 24 + i], top);
        #pragma unroll
        for (int i = 0; i < 4; i++)
            g_cand[(size_t)(base + t) * 8 + half * 4 + i] =
                (int)(top[i] & 0xffffffffu);
    }
}

// ---------------------------------------------------------------------------
// Rescore: exact fp32 distance for 8 candidates per token (warp per token)
// ---------------------------------------------------------------------------
__global__ void __launch_bounds__(256, 4) k_rescore(const float* __restrict__ emb) {
    const int t = threadIdx.x, wid = t >> 5, lane = t & 31;
    const int n = blockIdx.x * 8 + wid;
    const float4* xr = (const float4*)(g_xT + (size_t)n * DDIM + lane * 8);
    float4 xa = xr[0], xb = xr[1];
    float xn2 = g_xn2[n];
    u64 best = ~0ULL;
    #pragma unroll
    for (int i = 0; i < 8; i++) {
        int c = g_cand[(size_t)n * 8 + i];
        const float4* er = (const float4*)(emb + (size_t)c * DDIM + lane * 8);
        float4 ea = er[0], eb = er[1];
        float p = 0.f;
        p = fmaf(xa.x, ea.x, p); p = fmaf(xa.y, ea.y, p);
        p = fmaf(xa.z, ea.z, p); p = fmaf(xa.w, ea.w, p);
        p = fmaf(xb.x, eb.x, p); p = fmaf(xb.y, eb.y, p);
        p = fmaf(xb.z, eb.z, p); p = fmaf(xb.w, eb.w, p);
        #pragma unroll
        for (int o = 16; o > 0; o >>= 1) p += __shfl_xor_sync(0xffffffffu, p, o);
        float A = xn2 + __ldg(&g_enorm2[c]);
        float d = fmaf(-2.f, p, A);
        u64 pk = ((u64)__float_as_uint(d) << 32) | (unsigned)c;
        if (pk < best) best = pk;
    }
    __shared__ float wb[8];
    if (lane == 0) {
        g_idx[n] = (int)(best & 0xffffffffu);
        wb[wid] = __uint_as_float((unsigned)(best >> 32));
    }
    __syncthreads();
    if (t == 0) {
        float s = 0.f;
        #pragma unroll
        for (int i = 0; i < 8; i++) s += wb[i];
        g_partial[blockIdx.x] = s;
    }
}

// ---------------------------------------------------------------------------
// Gather + histogram
// ---------------------------------------------------------------------------
__global__ void __launch_bounds__(256, 1)
k_gather(const float* __restrict__ emb, float* __restrict__ out) {
    extern __shared__ float rows[];      // 128 * 257
    __shared__ int sidx[128];
    const int t = threadIdx.x;
    const int base = blockIdx.x * 128;
    if (t < 128) {
        int id = g_idx[base + t];
        sidx[t] = id;
        atomicAdd(&g_counts[id], 1);
    }
    __syncthreads();
    const int w = t >> 5, lane = t & 31;
    for (int r = w; r < 128; r += 8) {
        const float* er = emb + (size_t)sidx[r] * DDIM;
        #pragma unroll
        for (int q = 0; q < 8; q++)
            rows[r * 257 + lane + q * 32] = er[lane + q * 32];
    }
    __syncthreads();
    const int b = base >> 10, hw0 = base & 1023;
    float* ob = out + (size_t)b * (DDIM * HW) + hw0;
    const int m = t & 127, ch = t >> 7;
    #pragma unroll 4
    for (int cc = 0; cc < 128; cc++) {
        int c = cc * 2 + ch;
        ob[(size_t)c * HW + m] = rows[m * 257 + c];
    }
}

// ---------------------------------------------------------------------------
// Loss + perplexity
// ---------------------------------------------------------------------------
__global__ void k_final(float* __restrict__ out) {
    __shared__ float sh[1024];
    const int t = threadIdx.x;
    float s = 0.f;
    for (int i = t; i < NBRES; i += 1024) s += g_partial[i];
    sh[t] = s; __syncthreads();
    for (int o = 512; o > 0; o >>= 1) {
        if (t < o) sh[t] += sh[t + o];
        __syncthreads();
    }
    if (t == 0) out[OUT_ELEMS] = 1.25f * sh[0] / 16777216.0f;
    __syncthreads();
    float e = 0.f;
    for (int k = t; k < KCODES; k += 1024) {
        float p = (float)g_counts[k] * (1.0f / 65536.0f);
        e -= p * logf(p + 1e-10f);
    }
    sh[t] = e; __syncthreads();
    for (int o = 512; o > 0; o >>= 1) {
        if (t < o) sh[t] += sh[t + o];
        __syncthreads();
    }
    if (t == 0) out[OUT_ELEMS + 1] = expf(sh[0]);
}

// ---------------------------------------------------------------------------
extern "C" void kernel_launch(void* const* d_in, const int* in_sizes, int n_in,
                              void* d_out, int out_size) {
    const float* x   = (const float*)d_in[0];
    const float* emb = (const float*)d_in[1];
    float* out = (float*)d_out;

    const int SMEME = 128 * 260 * sizeof(float);   // 133120
    const int SMEMX = 256 * 132 * sizeof(float);   // 135168
    const int SMEMM = 4 * BSTAGE;                  // 65536 (B ring only)
    const int SMEMG = 128 * 257 * sizeof(float);   // 131584
    cudaFuncSetAttribute(k_prep_e, cudaFuncAttributeMaxDynamicSharedMemorySize, SMEME);
    cudaFuncSetAttribute(k_prep_x, cudaFuncAttributeMaxDynamicSharedMemorySize, SMEMX);
    cudaFuncSetAttribute(k_mma,    cudaFuncAttributeMaxDynamicSharedMemorySize, SMEMM);
    cudaFuncSetAttribute(k_gather, cudaFuncAttributeMaxDynamicSharedMemorySize, SMEMG);

    k_prep_e <<<KCODES / 128, 256, SMEME>>>(emb);
    k_prep_x <<<TOKENS / 128, 256, SMEMX>>>(x);
    k_mma    <<<NBMMA, 256, SMEMM>>>();
    k_rescore<<<NBRES, 256>>>(emb);
    k_gather <<<TOKENS / 128, 256, SMEMG>>>(emb, out);
    k_final  <<<1, 1024>>>(out);
}

// round 17
// speedup vs baseline: 1.3279x; 1.0245x over previous
#include <cuda_runtime.h>
#include <cuda_fp16.h>
#include <math.h>
#include <stdint.h>

#define TOKENS   65536
#define DDIM     256
#define KCODES   4096
#define HW       1024
#define OUT_ELEMS 16777216
#define NBMMA    2048            // 2 CTAs per 64-token block (code-space split)
#define NBRES    8192            // 8 tokens per CTA
#define BSTAGE   16384           // 32-code ntile: 16*4*32*2 u32 = 16KB
#define ESCALE   4096.0f         // e pre-scale (2^12, lossless)
#define DSCALE   (-2.0f / 4096.0f)
typedef unsigned long long u64;

// ---------------- global scratch ----------------
// fp16 A frags (m16n8k16): [mt(4096)][kt(16)][lane(32)][4] u32  (128 u32/token)
__device__ uint32_t g_x1f[TOKENS * 128];
// fp16 B frags (e * 4096): [nt(128)][kt(16)][nb(4)][lane(32)][2] u32
__device__ uint32_t g_e1f[128 * 4096];
__device__ float g_xT[TOKENS * DDIM];    // fp32 x token-major (rescore)
__device__ float g_xn2[TOKENS];
__device__ float g_enorm2[KCODES];
__device__ int   g_cand[TOKENS * 8];
__device__ int   g_idx[TOKENS];
__device__ float g_partial[NBRES];
__device__ int   g_counts[KCODES];

#define CP_ASYNC16(dst, src) \
    asm volatile("cp.async.cg.shared.global [%0], [%1], 16;" :: "r"(dst), "l"(src))
#define CP_COMMIT()  asm volatile("cp.async.commit_group;" ::: "memory")
#define CP_WAIT_0()  asm volatile("cp.async.wait_group 0;" ::: "memory")
#define CP_WAIT_1()  asm volatile("cp.async.wait_group 1;" ::: "memory")
#define CP_WAIT_2()  asm volatile("cp.async.wait_group 2;" ::: "memory")

__device__ __forceinline__ uint32_t su32(const void* p) {
    uint32_t a;
    asm("{ .reg .u64 t; cvta.to.shared.u64 t, %1; cvt.u32.u64 %0, t; }"
        : "=r"(a) : "l"(p));
    return a;
}
__device__ __forceinline__ uint32_t pack_hf2(float lo, float hi) {
    uint32_t l = (uint32_t)__half_as_ushort(__float2half(lo));
    uint32_t h = (uint32_t)__half_as_ushort(__float2half(hi));
    return l | (h << 16);
}
__device__ __forceinline__ void mma16816h(uint32_t* c, const uint32_t* a,
                                          uint32_t b0, uint32_t b1) {
    asm volatile(
        "mma.sync.aligned.m16n8k16.row.col.f16.f16.f16.f16 "
        "{%0,%1},{%2,%3,%4,%5},{%6,%7},{%0,%1};"
        : "+r"(c[0]), "+r"(c[1])
        : "r"(a[0]), "r"(a[1]), "r"(a[2]), "r"(a[3]), "r"(b0), "r"(b1));
}
__device__ __forceinline__ float hlo(uint32_t v) {
    return __half2float(__ushort_as_half((unsigned short)(v & 0xffff)));
}
__device__ __forceinline__ float hhi(uint32_t v) {
    return __half2float(__ushort_as_half((unsigned short)(v >> 16)));
}
__device__ __forceinline__ void ins3(u64 p, u64* s) {
    if (p >= s[2]) return;
    s[2] = p;
    if (s[2] < s[1]) { u64 t = s[1]; s[1] = s[2]; s[2] = t; }
    if (s[1] < s[0]) { u64 t = s[0]; s[0] = s[1]; s[1] = t; }
}
__device__ __forceinline__ void ins4(u64 p, u64* s) {
    if (p >= s[3]) return;
    s[3] = p;
    if (s[3] < s[2]) { u64 t = s[2]; s[2] = s[3]; s[3] = t; }
    if (s[2] < s[1]) { u64 t = s[1]; s[1] = s[2]; s[2] = t; }
    if (s[1] < s[0]) { u64 t = s[0]; s[0] = s[1]; s[1] = t; }
}

// ---------------------------------------------------------------------------
// Prep E: 128 codes (4 ntiles of 32) per CTA; |e|^2 + scaled fp16 frags; hist=0
// ---------------------------------------------------------------------------
__global__ void __launch_bounds__(256, 1) k_prep_e(const float* __restrict__ emb) {
    extern __shared__ float sp[];          // [128][260]
    const int t = threadIdx.x;
    const float* src = emb + (size_t)blockIdx.x * 128 * DDIM;
    #pragma unroll
    for (int j = 0; j < 32; j++) {
        int i = t + j * 256;
        int row = i >> 6, c4 = i & 63;
        float4 v = *(const float4*)(src + row * DDIM + c4 * 4);
        *(float4*)&sp[row * 260 + c4 * 4] = v;
    }
    __syncthreads();
    if (t < 128) {
        float s = 0.f;
        #pragma unroll 8
        for (int d = 0; d < DDIM; d++) { float v = sp[t * 260 + d]; s = fmaf(v, v, s); }
        g_enorm2[blockIdx.x * 128 + t] = s;
        g_counts[blockIdx.x * 128 + t] = 0;
    }
    // frag layout per 32-code ntile: i2 = ((kt*4+nb)*32+lane)*2 + reg
    uint32_t* dst = g_e1f + (size_t)blockIdx.x * 16384;
    #pragma unroll
    for (int j = 0; j < 64; j++) {
        int i = t + j * 256;               // 0..16383
        int snt = i >> 12, i2 = i & 4095;
        int reg = i2 & 1, lane = (i2 >> 1) & 31, nb = (i2 >> 6) & 3, kt = i2 >> 8;
        int gid = lane >> 2, tig = lane & 3;
        int nl = snt * 32 + nb * 8 + gid;  // local code 0..127
        int q = kt * 8 + reg * 4 + tig;    // k-pair
        dst[i] = pack_hf2(sp[nl * 260 + 2 * q] * ESCALE,
                          sp[nl * 260 + 2 * q + 1] * ESCALE);
    }
}

// ---------------------------------------------------------------------------
// Prep X: 64 tokens per CTA (occ 3): transpose, |x|^2, fp32 copy, fp16 frags
// ---------------------------------------------------------------------------
__global__ void __launch_bounds__(256, 3) k_prep_x(const float* __restrict__ x) {
    extern __shared__ float As[];   // [d(256)][m(64) pad 68]
    const int t = threadIdx.x;
    const int base = blockIdx.x * 64;
    const int b = base >> 10, hw0 = base & 1023;
    const float* xb = x + (size_t)b * (DDIM * HW) + hw0;
    {
        int lane4 = (t & 15) * 4, d0 = t >> 4;   // 16 d-rows per pass
        #pragma unroll
        for (int dd = 0; dd < DDIM; dd += 16) {
            int d = dd + d0;
            float4 v = *(const float4*)(xb + (size_t)d * HW + lane4);
            *(float4*)&As[d * 68 + lane4] = v;
        }
    }
    __syncthreads();
    if (t < 64) {
        float s = 0.f;
        #pragma unroll 8
        for (int d = 0; d < DDIM; d++) { float v = As[d * 68 + t]; s = fmaf(v, v, s); }
        g_xn2[base + t] = s;
    }
    // fp32 token-major copy: 64*256 floats
    #pragma unroll
    for (int j = 0; j < 64; j++) {
        int i = t + j * 256;
        int m = i >> 8, d = i & 255;
        g_xT[(size_t)(base + m) * DDIM + d] = As[d * 68 + m];
    }
    // frags: i = mtl*2048 + kt*128 + lane*4 + reg  (4 mtl, 128 u32/token)
    uint32_t* dst = g_x1f + (size_t)base * 128;
    #pragma unroll
    for (int j = 0; j < 32; j++) {
        int i = t + j * 256;
        int reg = i & 3, lane = (i >> 2) & 31, kt = (i >> 7) & 15, mtl = i >> 11;
        int gid = lane >> 2, tig = lane & 3;
        int rsel = reg & 1, khalf = reg >> 1;
        int m = mtl * 16 + rsel * 8 + gid;
        int q = kt * 8 + khalf * 4 + tig;
        dst[i] = pack_hf2(As[(2 * q) * 68 + m], As[(2 * q + 1) * 68 + m]);
    }
}

// ---------------------------------------------------------------------------
// Main: fp16 mma.sync, 64-token x half-codebook jobs, A in registers,
// 4-stage B ring, 1 barrier/ntile. SMEM: 4 x 16KB.
// CTA = (block >> 1) token-block, (block & 1) code half -> cand slots 0-3/4-7
// ---------------------------------------------------------------------------
__device__ __forceinline__ void load_b(uint32_t smb, int nt, int t) {
    const char* src = (const char*)g_e1f + (size_t)nt * 16384;
    uint32_t dst = smb + (nt & 3) * BSTAGE;
    #pragma unroll
    for (int j = 0; j < 4; j++) {
        int c = t + j * 256;               // linear copy
        CP_ASYNC16(dst + c * 16, src + c * 16);
    }
}

__global__ void __launch_bounds__(256, 2) k_mma() {
    extern __shared__ char sm[];
    const uint32_t smb = su32(sm);
    const int t = threadIdx.x, wid = t >> 5, lane = t & 31;
    const int gid = lane >> 2, tig = lane & 3;
    const int base = (blockIdx.x >> 1) * 64;
    const int half = blockIdx.x & 1;
    const int nt0  = half * 64;             // ntile range [nt0, nt0+64)
    const int mt = wid & 3;                 // local m-tile (16 tokens)
    const int h  = wid >> 2;                // nb pair: nb = h*2, h*2+1

    // prologue: 3-deep B prefetch
    load_b(smb, nt0 + 0, t); CP_COMMIT();
    load_b(smb, nt0 + 1, t); CP_COMMIT();
    load_b(smb, nt0 + 2, t); CP_COMMIT();

    // A fragments resident in registers for the whole loop (reused 64x)
    uint32_t A[16][4];
    {
        const uint32_t* asrc = g_x1f + (size_t)base * 128 + mt * 2048 + lane * 4;
        #pragma unroll
        for (int kt = 0; kt < 16; kt++)
            *(uint4*)A[kt] = *(const uint4*)(asrc + kt * 128);
    }

    const int tk0 = base + mt * 16 + gid;
    const float xr0 = g_xn2[tk0], xr1 = g_xn2[tk0 + 8];

    u64 L[2][3];
    #pragma unroll
    for (int l = 0; l < 2; l++)
        #pragma unroll
        for (int i = 0; i < 3; i++) L[l][i] = ~0ULL;

    for (int ii = 0; ii < 64; ii++) {
        const int nt = nt0 + ii;
        if (ii <= 61)      { CP_WAIT_2(); }
        else if (ii == 62) { CP_WAIT_1(); }
        else               { CP_WAIT_0(); }
        __syncthreads();                       // publish loads + retire prev
        if (ii + 3 < 64) { load_b(smb, nt + 3, t); CP_COMMIT(); }

        const uint32_t* Bf = (const uint32_t*)(sm + (nt & 3) * BSTAGE);
        uint32_t acc[2][2];                    // fp16x2 accumulators
        acc[0][0] = acc[0][1] = acc[1][0] = acc[1][1] = 0u;

        #pragma unroll
        for (int kt = 0; kt < 16; kt++) {
            uint2 b0 = *(const uint2*)(Bf + ((kt * 4 + h * 2 + 0) * 32 + lane) * 2);
            uint2 b1 = *(const uint2*)(Bf + ((kt * 4 + h * 2 + 1) * 32 + lane) * 2);
            mma16816h(acc[0], A[kt], b0.x, b0.y);
            mma16816h(acc[1], A[kt], b1.x, b1.y);
        }

        // fold: d = fma(DSCALE, dot_scaled, xn2 + en2); codes ascending; '<'
        #pragma unroll
        for (int nb2 = 0; nb2 < 2; nb2++) {
            int code0 = nt * 32 + (h * 2 + nb2) * 8 + tig * 2;
            float en0 = __ldg(&g_enorm2[code0]);
            float en1 = __ldg(&g_enorm2[code0 + 1]);
            float d;
            d = fmaf(DSCALE, hlo(acc[nb2][0]), xr0 + en0);
            ins3(((u64)__float_as_uint(d) << 32) | (unsigned)code0,       L[0]);
            d = fmaf(DSCALE, hhi(acc[nb2][0]), xr0 + en1);
            ins3(((u64)__float_as_uint(d) << 32) | (unsigned)(code0 + 1), L[0]);
            d = fmaf(DSCALE, hlo(acc[nb2][1]), xr1 + en0);
            ins3(((u64)__float_as_uint(d) << 32) | (unsigned)code0,       L[1]);
            d = fmaf(DSCALE, hhi(acc[nb2][1]), xr1 + en1);
            ins3(((u64)__float_as_uint(d) << 32) | (unsigned)(code0 + 1), L[1]);
        }
    }

    // merge: 8 buckets (h,tig) x top-3 per token -> top-4 of this code half
    __syncthreads();
    u64* cm = (u64*)sm;                        // [64][24] = 12KB (reuses B ring)
    #pragma unroll
    for (int l = 0; l < 2; l++) {
        int tok = mt * 16 + l * 8 + gid;
        #pragma unroll
        for (int i = 0; i < 3; i++)
            cm[(size_t)tok * 24 + (h * 4 + tig) * 3 + i] = L[l][i];
    }
    __syncthreads();
    if (t < 64) {
        u64 top[4];
        #pragma unroll
        for (int i = 0; i < 4; i++) top[i] = ~0ULL;
        #pragma unroll
        for (int i = 0; i < 24; i++) ins4(cm[(size_t)t * 24 + i], top);
        #pragma unroll
        for (int i = 0; i < 4; i++)
            g_cand[(size_t)(base + t) * 8 + half * 4 + i] =
                (int)(top[i] & 0xffffffffu);
    }
}

// ---------------------------------------------------------------------------
// Rescore: exact fp32 distance for 8 candidates per token (warp per token)
// ---------------------------------------------------------------------------
__global__ void __launch_bounds__(256, 4) k_rescore(const float* __restrict__ emb) {
    const int t = threadIdx.x, wid = t >> 5, lane = t & 31;
    const int n = blockIdx.x * 8 + wid;
    const float4* xr = (const float4*)(g_xT + (size_t)n * DDIM + lane * 8);
    float4 xa = xr[0], xb = xr[1];
    float xn2 = g_xn2[n];
    u64 best = ~0ULL;
    #pragma unroll
    for (int i = 0; i < 8; i++) {
        int c = g_cand[(size_t)n * 8 + i];
        const float4* er = (const float4*)(emb + (size_t)c * DDIM + lane * 8);
        float4 ea = er[0], eb = er[1];
        float p = 0.f;
        p = fmaf(xa.x, ea.x, p); p = fmaf(xa.y, ea.y, p);
        p = fmaf(xa.z, ea.z, p); p = fmaf(xa.w, ea.w, p);
        p = fmaf(xb.x, eb.x, p); p = fmaf(xb.y, eb.y, p);
        p = fmaf(xb.z, eb.z, p); p = fmaf(xb.w, eb.w, p);
        #pragma unroll
        for (int o = 16; o > 0; o >>= 1) p += __shfl_xor_sync(0xffffffffu, p, o);
        float A = xn2 + __ldg(&g_enorm2[c]);
        float d = fmaf(-2.f, p, A);
        u64 pk = ((u64)__float_as_uint(d) << 32) | (unsigned)c;
        if (pk < best) best = pk;
    }
    __shared__ float wb[8];
    if (lane == 0) {
        g_idx[n] = (int)(best & 0xffffffffu);
        wb[wid] = __uint_as_float((unsigned)(best >> 32));
    }
    __syncthreads();
    if (t == 0) {
        float s = 0.f;
        #pragma unroll
        for (int i = 0; i < 8; i++) s += wb[i];
        g_partial[blockIdx.x] = s;
    }
}

// ---------------------------------------------------------------------------
// Gather + histogram: 64-token tiles (occ 3)
// ---------------------------------------------------------------------------
__global__ void __launch_bounds__(256, 3)
k_gather(const float* __restrict__ emb, float* __restrict__ out) {
    extern __shared__ float rows[];      // [64][257]
    __shared__ int sidx[64];
    const int t = threadIdx.x;
    const int base = blockIdx.x * 64;
    if (t < 64) {
        int id = g_idx[base + t];
        sidx[t] = id;
        atomicAdd(&g_counts[id], 1);
    }
    __syncthreads();
    const int w = t >> 5, lane = t & 31;
    for (int r = w; r < 64; r += 8) {
        const float* er = emb + (size_t)sidx[r] * DDIM;
        #pragma unroll
        for (int q = 0; q < 8; q++)
            rows[r * 257 + lane + q * 32] = er[lane + q * 32];
    }
    __syncthreads();
    const int b = base >> 10, hw0 = base & 1023;
    float* ob = out + (size_t)b * (DDIM * HW) + hw0;
    const int m = t & 63, ch = t >> 6;       // 4 channel groups
    #pragma unroll 4
    for (int cc = 0; cc < 64; cc++) {
        int c = cc * 4 + ch;
        ob[(size_t)c * HW + m] = rows[m * 257 + c];
    }
}

// ---------------------------------------------------------------------------
// Loss + perplexity
// ---------------------------------------------------------------------------
__global__ void k_final(float* __restrict__ out) {
    __shared__ float sh[1024];
    const int t = threadIdx.x;
    float s = 0.f;
    for (int i = t; i < NBRES; i += 1024) s += g_partial[i];
    sh[t] = s; __syncthreads();
    for (int o = 512; o > 0; o >>= 1) {
        if (t < o) sh[t] += sh[t + o];
        __syncthreads();
    }
    if (t == 0) out[OUT_ELEMS] = 1.25f * sh[0] / 16777216.0f;
    __syncthreads();
    float e = 0.f;
    for (int k = t; k < KCODES; k += 1024) {
        float p = (float)g_counts[k] * (1.0f / 65536.0f);
        e -= p * logf(p + 1e-10f);
    }
    sh[t] = e; __syncthreads();
    for (int o = 512; o > 0; o >>= 1) {
        if (t < o) sh[t] += sh[t + o];
        __syncthreads();
    }
    if (t == 0) out[OUT_ELEMS + 1] = expf(sh[0]);
}

// ---------------------------------------------------------------------------
extern "C" void kernel_launch(void* const* d_in, const int* in_sizes, int n_in,
                              void* d_out, int out_size) {
    const float* x   = (const float*)d_in[0];
    const float* emb = (const float*)d_in[1];
    float* out = (float*)d_out;

    const int SMEME = 128 * 260 * sizeof(float);   // 133120
    const int SMEMX = 256 * 68 * sizeof(float);    // 69632  -> 3 CTAs/SM
    const int SMEMM = 4 * BSTAGE;                  // 65536  -> 2 CTAs/SM
    const int SMEMG = 64 * 257 * sizeof(float);    // 65792  -> 3 CTAs/SM
    cudaFuncSetAttribute(k_prep_e, cudaFuncAttributeMaxDynamicSharedMemorySize, SMEME);
    cudaFuncSetAttribute(k_prep_x, cudaFuncAttributeMaxDynamicSharedMemorySize, SMEMX);
    cudaFuncSetAttribute(k_mma,    cudaFuncAttributeMaxDynamicSharedMemorySize, SMEMM);
    cudaFuncSetAttribute(k_gather, cudaFuncAttributeMaxDynamicSharedMemorySize, SMEMG);

    k_prep_e <<<KCODES / 128, 256, SMEME>>>(emb);
    k_prep_x <<<TOKENS / 64, 256, SMEMX>>>(x);
    k_mma    <<<NBMMA, 256, SMEMM>>>();
    k_rescore<<<NBRES, 256>>>(emb);
    k_gather <<<TOKENS / 64, 256, SMEMG>>>(emb, out);
    k_final  <<<1, 1024>>>(out);
}